// round 8
// baseline (speedup 1.0000x reference)
#include <cuda_runtime.h>
#include <math.h>
#include <stdint.h>

#define NN 100000
#define EE 1600000
#define GG 128
#define LL 8
#define DD 128
#define AA 28
#define EPSF 1e-5f

// ---------------- scratch (device globals; no allocation allowed) ----------
__device__ float g_bufA[NN * DD];     // h_pre (pre-BN output of each layer)
__device__ float g_bufQ[NN * DD];     // q = aggregated p (fp32)
__device__ short g_p[NN * DD];        // p = tanh(BN(h))*ns quantized Q15
__device__ float2 g_xns[NN];          // {ns, as_float(x)} packed for layer-0 gather
__device__ float g_ew0[AA * DD];      // embed @ W0
__device__ int   g_out_deg[NN];
__device__ int   g_in_deg[NN];
__device__ float g_ns[NN];
__device__ float g_nd[NN];
__device__ int   g_row_ptr[NN + 1];
__device__ int   g_cursor[NN];
__device__ int   g_csr_src[EE];
__device__ float g_bn_sum[LL][DD];
__device__ float g_bn_sq[LL][DD];
__device__ float g_pool_sum[GG * DD];
__device__ float g_pool_cnt[GG];

// ---------------- init ----------
__global__ void k_init() {
    int i = blockIdx.x * blockDim.x + threadIdx.x;
    int stride = gridDim.x * blockDim.x;
    for (int j = i; j < NN; j += stride) { g_out_deg[j] = 0; g_in_deg[j] = 0; }
    for (int j = i; j < LL * DD; j += stride) {
        ((float*)g_bn_sum)[j] = 0.f;
        ((float*)g_bn_sq)[j] = 0.f;
    }
    for (int j = i; j < GG * DD; j += stride) g_pool_sum[j] = 0.f;
    for (int j = i; j < GG; j += stride) g_pool_cnt[j] = 0.f;
}

// ---------------- degree counting ----------
__global__ void k_degree(const int* __restrict__ src, const int* __restrict__ dst) {
    int i = blockIdx.x * blockDim.x + threadIdx.x;
    if (i < EE) {
        atomicAdd(&g_out_deg[src[i]], 1);
        atomicAdd(&g_in_deg[dst[i]], 1);
    }
}

// ---------------- single-block exclusive scan of in-degree -> row_ptr ------
__global__ void k_scan() {
    __shared__ int wsum[32];
    __shared__ int s_running;
    int tid = threadIdx.x, lane = tid & 31, wid = tid >> 5;
    if (tid == 0) s_running = 0;
    __syncthreads();
    for (int base = 0; base < NN; base += 1024) {
        int i = base + tid;
        int v = (i < NN) ? g_in_deg[i] : 0;
        int incl = v;
#pragma unroll
        for (int off = 1; off < 32; off <<= 1) {
            int t = __shfl_up_sync(0xffffffffu, incl, off);
            if (lane >= off) incl += t;
        }
        if (lane == 31) wsum[wid] = incl;
        __syncthreads();
        if (wid == 0) {
            int s = wsum[lane];
#pragma unroll
            for (int off = 1; off < 32; off <<= 1) {
                int t = __shfl_up_sync(0xffffffffu, s, off);
                if (lane >= off) s += t;
            }
            wsum[lane] = s;
        }
        __syncthreads();
        int woff = wid ? wsum[wid - 1] : 0;
        int run = s_running;
        int excl = run + woff + incl - v;
        if (i < NN) { g_row_ptr[i] = excl; g_cursor[i] = excl; }
        __syncthreads();
        if (tid == 0) s_running = run + wsum[31];
        __syncthreads();
    }
    if (threadIdx.x == 0) g_row_ptr[NN] = s_running;
}

// ---------------- norms + packed (ns,x) ----------
__global__ void k_norms(const int* __restrict__ x) {
    int i = blockIdx.x * blockDim.x + threadIdx.x;
    if (i < NN) {
        float ns = rsqrtf((float)max(g_out_deg[i], 1));
        g_ns[i] = ns;
        g_nd[i] = rsqrtf((float)max(g_in_deg[i], 1));
        g_xns[i] = make_float2(ns, __int_as_float(x[i]));
    }
}

// ---------------- CSR fill ----------
__global__ void k_fill(const int* __restrict__ src, const int* __restrict__ dst) {
    int i = blockIdx.x * blockDim.x + threadIdx.x;
    if (i < EE) {
        int d = dst[i];
        int p = atomicAdd(&g_cursor[d], 1);
        g_csr_src[p] = src[i];
    }
}

// ---------------- EW0 = embed @ W0  (28 x 128) ----------
__global__ void k_ew0(const float* __restrict__ embed, const float* __restrict__ W0) {
    int a = blockIdx.x;      // 0..27
    int f = threadIdx.x;     // 0..127
    float acc = 0.f;
#pragma unroll 8
    for (int k = 0; k < DD; k++)
        acc = fmaf(embed[a * DD + k], W0[k * DD + f], acc);
    g_ew0[a * DD + f] = acc;
}

// ---------------- layer-0 fused agg+gemm: h_pre0 = (Σ EW0[x[s]]*ns[s])*nd+b0, *snorm
__global__ void k_agg0(const float* __restrict__ bs,
                       const float* __restrict__ snorm_n) {
    __shared__ float s_ew[AA * DD];
    __shared__ float s_sum[8][DD];
    __shared__ float s_sq[8][DD];
    int tid = threadIdx.x;
    int w = tid >> 5;
    int lane = tid & 31;
    int node = blockIdx.x * 8 + w;

    for (int i = tid; i < AA * DD; i += 256) s_ew[i] = g_ew0[i];
    __syncthreads();

    float4 r = {0.f, 0.f, 0.f, 0.f};
    if (node < NN) {
        float4 acc = {0.f, 0.f, 0.f, 0.f};
        int start = g_row_ptr[node];
        int end = g_row_ptr[node + 1];
        for (int base = start; base < end; base += 32) {
            int e = base + lane;
            float2 xn = {0.f, 0.f};
            if (e < end) xn = g_xns[g_csr_src[e]];
            int cnt = min(32, end - base);
            for (int j = 0; j < cnt; j++) {
                float nj = __shfl_sync(0xffffffffu, xn.x, j);
                int xj = __shfl_sync(0xffffffffu, __float_as_int(xn.y), j);
                float4 v = *(const float4*)&s_ew[xj * DD + lane * 4];
                acc.x = fmaf(v.x, nj, acc.x);
                acc.y = fmaf(v.y, nj, acc.y);
                acc.z = fmaf(v.z, nj, acc.z);
                acc.w = fmaf(v.w, nj, acc.w);
            }
        }
        float ndv = g_nd[node];
        float sn = snorm_n[node];
        float4 b = *(const float4*)&bs[0 * DD + lane * 4];
        r.x = fmaf(acc.x, ndv, b.x) * sn;
        r.y = fmaf(acc.y, ndv, b.y) * sn;
        r.z = fmaf(acc.z, ndv, b.z) * sn;
        r.w = fmaf(acc.w, ndv, b.w) * sn;
        *(float4*)&g_bufA[node * DD + lane * 4] = r;
    }
    int f0 = lane * 4;
    s_sum[w][f0] = r.x; s_sum[w][f0 + 1] = r.y; s_sum[w][f0 + 2] = r.z; s_sum[w][f0 + 3] = r.w;
    s_sq[w][f0] = r.x * r.x; s_sq[w][f0 + 1] = r.y * r.y;
    s_sq[w][f0 + 2] = r.z * r.z; s_sq[w][f0 + 3] = r.w * r.w;
    __syncthreads();
    if (tid < DD) {
        float s = 0.f, q = 0.f;
#pragma unroll
        for (int ww = 0; ww < 8; ww++) { s += s_sum[ww][tid]; q += s_sq[ww][tid]; }
        atomicAdd(&g_bn_sum[0][tid], s);
        atomicAdd(&g_bn_sq[0][tid], q);
    }
}

// ---------------- quantize: p = Q15( tanh(BN_layer(h_pre)) * ns ) ----------
// block = 256 threads handles 8 rows (each thread one float4 quad).
__global__ __launch_bounds__(256) void k_quant(const float* __restrict__ gammas,
                                               const float* __restrict__ betas,
                                               int layer) {
    __shared__ float s_scale[DD];
    __shared__ float s_shift[DD];
    int tid = threadIdx.x;
    if (tid < DD) {
        float mean = g_bn_sum[layer][tid] * (1.f / NN);
        float var = g_bn_sq[layer][tid] * (1.f / NN) - mean * mean;
        float rstd = rsqrtf(var + EPSF);
        float sc = rstd * gammas[layer * DD + tid];
        s_scale[tid] = sc;
        s_shift[tid] = betas[layer * DD + tid] - mean * sc;
    }
    __syncthreads();
    int idx = blockIdx.x * 256 + tid;      // quad index
    int row = idx >> 5;
    int quad = idx & 31;
    if (row >= NN) return;
    float ns = g_ns[row];
    float4 v = *(const float4*)&g_bufA[row * DD + quad * 4];
    int f = quad * 4;
    float p0 = tanhf(fmaf(v.x, s_scale[f], s_shift[f])) * ns;
    float p1 = tanhf(fmaf(v.y, s_scale[f + 1], s_shift[f + 1])) * ns;
    float p2 = tanhf(fmaf(v.z, s_scale[f + 2], s_shift[f + 2])) * ns;
    float p3 = tanhf(fmaf(v.w, s_scale[f + 3], s_shift[f + 3])) * ns;
    short4 o;
    o.x = (short)min(32767, __float2int_rn(p0 * 32768.f));
    o.y = (short)min(32767, __float2int_rn(p1 * 32768.f));
    o.z = (short)min(32767, __float2int_rn(p2 * 32768.f));
    o.w = (short)min(32767, __float2int_rn(p3 * 32768.f));
    *(short4*)&g_p[row * DD + f] = o;
}

// ---------------- int16 gather-sum: q[d] = Σ p[src] (exact int32) ----------
__global__ void k_agg16() {
    int w = threadIdx.x >> 5;
    int lane = threadIdx.x & 31;
    int node = blockIdx.x * 8 + w;
    if (node >= NN) return;
    int ax = 0, ay = 0, az = 0, aw = 0;
    int start = g_row_ptr[node];
    int end = g_row_ptr[node + 1];
    for (int base = start; base < end; base += 32) {
        int e = base + lane;
        int s = (e < end) ? g_csr_src[e] : 0;
        int cnt = min(32, end - base);
        int j = 0;
        for (; j + 8 <= cnt; j += 8) {
            int s0 = __shfl_sync(0xffffffffu, s, j);
            int s1 = __shfl_sync(0xffffffffu, s, j + 1);
            int s2 = __shfl_sync(0xffffffffu, s, j + 2);
            int s3 = __shfl_sync(0xffffffffu, s, j + 3);
            int s4 = __shfl_sync(0xffffffffu, s, j + 4);
            int s5 = __shfl_sync(0xffffffffu, s, j + 5);
            int s6 = __shfl_sync(0xffffffffu, s, j + 6);
            int s7 = __shfl_sync(0xffffffffu, s, j + 7);
            short4 v0 = *(const short4*)&g_p[s0 * DD + lane * 4];
            short4 v1 = *(const short4*)&g_p[s1 * DD + lane * 4];
            short4 v2 = *(const short4*)&g_p[s2 * DD + lane * 4];
            short4 v3 = *(const short4*)&g_p[s3 * DD + lane * 4];
            short4 v4 = *(const short4*)&g_p[s4 * DD + lane * 4];
            short4 v5 = *(const short4*)&g_p[s5 * DD + lane * 4];
            short4 v6 = *(const short4*)&g_p[s6 * DD + lane * 4];
            short4 v7 = *(const short4*)&g_p[s7 * DD + lane * 4];
            ax += (v0.x + v1.x) + (v2.x + v3.x) + (v4.x + v5.x) + (v6.x + v7.x);
            ay += (v0.y + v1.y) + (v2.y + v3.y) + (v4.y + v5.y) + (v6.y + v7.y);
            az += (v0.z + v1.z) + (v2.z + v3.z) + (v4.z + v5.z) + (v6.z + v7.z);
            aw += (v0.w + v1.w) + (v2.w + v3.w) + (v4.w + v5.w) + (v6.w + v7.w);
        }
        for (; j < cnt; j++) {
            int sj = __shfl_sync(0xffffffffu, s, j);
            short4 v = *(const short4*)&g_p[sj * DD + lane * 4];
            ax += v.x; ay += v.y; az += v.z; aw += v.w;
        }
    }
    const float INV = 1.f / 32768.f;
    float4 q = {ax * INV, ay * INV, az * INV, aw * INV};
    *(float4*)&g_bufQ[node * DD + lane * 4] = q;
}

// ---------------- 3xBF16 tensor-core GEMM (layers 1..7) --------------------
// h_pre = (q @ W)*nd + b, *snorm; BN stats in epilogue.
__device__ __forceinline__ void mma_bf16(float* c, uint32_t a0, uint32_t a1,
                                         uint32_t a2, uint32_t a3,
                                         uint32_t b0, uint32_t b1) {
    asm volatile(
        "mma.sync.aligned.m16n8k16.row.col.f32.bf16.bf16.f32 "
        "{%0,%1,%2,%3}, {%4,%5,%6,%7}, {%8,%9}, {%0,%1,%2,%3};\n"
        : "+f"(c[0]), "+f"(c[1]), "+f"(c[2]), "+f"(c[3])
        : "r"(a0), "r"(a1), "r"(a2), "r"(a3), "r"(b0), "r"(b1));
}

__device__ __forceinline__ uint32_t pack_bf16(float x, float y) {
    uint32_t r;
    asm("cvt.rn.bf16x2.f32 %0, %1, %2;" : "=r"(r) : "f"(y), "f"(x));
    return r;
}

__device__ __forceinline__ void split2(float x, float y, uint32_t& hi, uint32_t& lo) {
    hi = pack_bf16(x, y);
    float hx = __uint_as_float(hi << 16);
    float hy = __uint_as_float(hi & 0xffff0000u);
    lo = pack_bf16(x - hx, y - hy);
}

#define PSTR 18

__global__ __launch_bounds__(256) void k_gemm(const float* __restrict__ W,
                                              const float* __restrict__ bs,
                                              const float* __restrict__ snorm_n,
                                              int layer) {
    __shared__ uint32_t As_hi[128 * PSTR];
    __shared__ uint32_t As_lo[128 * PSTR];
    __shared__ uint32_t Wt_hi[128 * PSTR];
    __shared__ uint32_t Wt_lo[128 * PSTR];
    __shared__ float s_sum[DD];
    __shared__ float s_sq[DD];

    int tid = threadIdx.x;
    int wid = tid >> 5;
    int lane = tid & 31;
    int g = lane >> 2;
    int tig = lane & 3;
    int row0 = blockIdx.x * 128;
    int wrow = wid * 16;

    if (tid < DD) { s_sum[tid] = 0.f; s_sq[tid] = 0.f; }

    float c[16][4];
#pragma unroll
    for (int i = 0; i < 16; i++)
#pragma unroll
        for (int j = 0; j < 4; j++) c[i][j] = 0.f;

    for (int k0 = 0; k0 < DD; k0 += 32) {
        for (int idx = tid; idx < 128 * 8; idx += 256) {
            int r = idx >> 3;
            int k4 = (idx & 7) * 4;
            int row = row0 + r;
            float4 v = {0.f, 0.f, 0.f, 0.f};
            if (row < NN) v = *(const float4*)&g_bufQ[row * DD + k0 + k4];
            uint32_t h01, l01, h23, l23;
            split2(v.x, v.y, h01, l01);
            split2(v.z, v.w, h23, l23);
            int p = r * PSTR + (k4 >> 1);
            As_hi[p] = h01; As_hi[p + 1] = h23;
            As_lo[p] = l01; As_lo[p + 1] = l23;
        }
        for (int idx = tid; idx < 16 * DD; idx += 256) {
            int n = idx & 127;
            int kp = idx >> 7;
            float w0 = W[(k0 + 2 * kp) * DD + n];
            float w1 = W[(k0 + 2 * kp + 1) * DD + n];
            uint32_t h, l;
            split2(w0, w1, h, l);
            Wt_hi[n * PSTR + kp] = h;
            Wt_lo[n * PSTR + kp] = l;
        }
        __syncthreads();
#pragma unroll
        for (int ks = 0; ks < 2; ks++) {
            int kb = ks * 8;
            int ra = (wrow + g) * PSTR + kb + tig;
            int rb = (wrow + g + 8) * PSTR + kb + tig;
            uint32_t ah0 = As_hi[ra],     ah1 = As_hi[rb];
            uint32_t ah2 = As_hi[ra + 4], ah3 = As_hi[rb + 4];
            uint32_t al0 = As_lo[ra],     al1 = As_lo[rb];
            uint32_t al2 = As_lo[ra + 4], al3 = As_lo[rb + 4];
#pragma unroll
            for (int nt = 0; nt < 16; nt++) {
                int wb = (nt * 8 + g) * PSTR + kb + tig;
                uint32_t bh0 = Wt_hi[wb], bh1 = Wt_hi[wb + 4];
                uint32_t bl0 = Wt_lo[wb], bl1 = Wt_lo[wb + 4];
                mma_bf16(c[nt], al0, al1, al2, al3, bh0, bh1);
                mma_bf16(c[nt], ah0, ah1, ah2, ah3, bl0, bl1);
                mma_bf16(c[nt], ah0, ah1, ah2, ah3, bh0, bh1);
            }
        }
        __syncthreads();
    }
    // epilogue: h = (c*nd + b)*snorm, store + BN stats
    int rA = row0 + wrow + g;
    int rB = rA + 8;
    bool vA = rA < NN, vB = rB < NN;
    float ndA = vA ? g_nd[rA] : 0.f;
    float ndB = vB ? g_nd[rB] : 0.f;
    float snA = vA ? snorm_n[rA] : 0.f;
    float snB = vB ? snorm_n[rB] : 0.f;
#pragma unroll
    for (int nt = 0; nt < 16; nt++) {
        int col = nt * 8 + tig * 2;
        float b0 = bs[layer * DD + col];
        float b1 = bs[layer * DD + col + 1];
        float hA0 = 0.f, hA1 = 0.f, hB0 = 0.f, hB1 = 0.f;
        if (vA) {
            hA0 = fmaf(c[nt][0], ndA, b0) * snA;
            hA1 = fmaf(c[nt][1], ndA, b1) * snA;
            float2 o = {hA0, hA1};
            *(float2*)&g_bufA[rA * DD + col] = o;
        }
        if (vB) {
            hB0 = fmaf(c[nt][2], ndB, b0) * snB;
            hB1 = fmaf(c[nt][3], ndB, b1) * snB;
            float2 o = {hB0, hB1};
            *(float2*)&g_bufA[rB * DD + col] = o;
        }
        atomicAdd(&s_sum[col], hA0 + hB0);
        atomicAdd(&s_sum[col + 1], hA1 + hB1);
        atomicAdd(&s_sq[col], hA0 * hA0 + hB0 * hB0);
        atomicAdd(&s_sq[col + 1], hA1 * hA1 + hB1 * hB1);
    }
    __syncthreads();
    if (tid < DD) {
        atomicAdd(&g_bn_sum[layer][tid], s_sum[tid]);
        atomicAdd(&g_bn_sq[layer][tid], s_sq[tid]);
    }
}

// ---------------- graph mean pooling (graph_ids sorted); BN folded in ------
__global__ void k_pool(const int* __restrict__ gid,
                       const float* __restrict__ gammas,
                       const float* __restrict__ betas) {
    int f = threadIdx.x;
    int base = blockIdx.x * 32;
    float mean = g_bn_sum[LL - 1][f] * (1.f / NN);
    float var = g_bn_sq[LL - 1][f] * (1.f / NN) - mean * mean;
    float rstd = rsqrtf(var + EPSF);
    float sc = rstd * gammas[(LL - 1) * DD + f];
    float sh = betas[(LL - 1) * DD + f] - mean * sc;

    float acc = 0.f;
    int cur = gid[base];
    for (int i = 0; i < 32; i++) {
        int node = base + i;
        if (node >= NN) break;
        int g = gid[node];
        if (g != cur) {
            atomicAdd(&g_pool_sum[cur * DD + f], acc);
            acc = 0.f;
            cur = g;
        }
        float v = g_bufA[node * DD + f];
        acc += tanhf(fmaf(v, sc, sh));
    }
    atomicAdd(&g_pool_sum[cur * DD + f], acc);
    if (f == 0) {
        float c = 0.f;
        int cur2 = gid[base];
        for (int i = 0; i < 32; i++) {
            int node = base + i;
            if (node >= NN) break;
            int g = gid[node];
            if (g != cur2) {
                atomicAdd(&g_pool_cnt[cur2], c);
                c = 0.f;
                cur2 = g;
            }
            c += 1.f;
        }
        atomicAdd(&g_pool_cnt[cur2], c);
    }
}

// ---------------- readout MLP ----------
__global__ void k_mlp(const float* __restrict__ r1w, const float* __restrict__ r1b,
                      const float* __restrict__ r2w, const float* __restrict__ r2b,
                      float* __restrict__ out) {
    __shared__ float hg[DD];
    __shared__ float z[64];
    int g = blockIdx.x;
    int t = threadIdx.x;
    float cnt = fmaxf(g_pool_cnt[g], 1.f);
    for (int f = t; f < DD; f += 64)
        hg[f] = fmaxf(g_pool_sum[g * DD + f] / cnt, 0.f);
    __syncthreads();
    float d = r1b[t];
#pragma unroll 8
    for (int f = 0; f < DD; f++) d = fmaf(hg[f], r1w[t * DD + f], d);
    z[t] = fmaxf(d, 0.f);
    __syncthreads();
    if (t == 0) {
        float o = r2b[0];
#pragma unroll 8
        for (int i = 0; i < 64; i++) o = fmaf(z[i], r2w[i], o);
        out[g] = o;
    }
}

// ---------------- host ----------
extern "C" void kernel_launch(void* const* d_in, const int* in_sizes, int n_in,
                              void* d_out, int out_size) {
    const int* x = (const int*)d_in[0];
    const int* src = (const int*)d_in[2];
    const int* dst = (const int*)d_in[3];
    const int* gid = (const int*)d_in[4];
    const float* snorm_n = (const float*)d_in[5];
    const float* embed = (const float*)d_in[7];
    const float* Ws = (const float*)d_in[8];
    const float* bs = (const float*)d_in[9];
    const float* gammas = (const float*)d_in[10];
    const float* betas = (const float*)d_in[11];
    const float* r1w = (const float*)d_in[12];
    const float* r1b = (const float*)d_in[13];
    const float* r2w = (const float*)d_in[14];
    const float* r2b = (const float*)d_in[15];
    float* out = (float*)d_out;

    k_init<<<256, 256>>>();
    k_ew0<<<AA, DD>>>(embed, Ws);
    k_degree<<<(EE + 255) / 256, 256>>>(src, dst);
    k_scan<<<1, 1024>>>();
    k_norms<<<(NN + 255) / 256, 256>>>(x);
    k_fill<<<(EE + 255) / 256, 256>>>(src, dst);

    // layer 0: fused lookup-aggregate (28-row embed table @ W0 in smem)
    k_agg0<<<(NN + 7) / 8, 256>>>(bs, snorm_n);

    for (int l = 1; l < LL; l++) {
        k_quant<<<(NN * 32 + 255) / 256, 256>>>(gammas, betas, l - 1);
        k_agg16<<<(NN + 7) / 8, 256>>>();
        k_gemm<<<(NN + 127) / 128, 256>>>(Ws + l * DD * DD, bs, snorm_n, l);
    }
    k_pool<<<(NN + 31) / 32, DD>>>(gid, gammas, betas);
    k_mlp<<<GG, 64>>>(r1w, r1b, r2w, r2b, out);
}

// round 9
// speedup vs baseline: 1.5203x; 1.5203x over previous
#include <cuda_runtime.h>
#include <math.h>
#include <stdint.h>

#define NN 100000
#define EE 1600000
#define GG 128
#define LL 8
#define DD 128
#define AA 28
#define EPSF 1e-5f
#define NB 98   // scan blocks of 1024

// ---------------- scratch ----------
__device__ float g_bufA[NN * DD];   // pre-BN node features per layer
__device__ float g_bufB[NN * DD];   // hw = tanh(BN(h)) @ W * ns
__device__ float2 g_xns[NN];        // {ns, as_float(x)} for layer-0 gather
__device__ float g_ew0[AA * DD];    // embed @ W0
__device__ int   g_out_deg[NN];
__device__ int   g_in_deg[NN];
__device__ float g_ns[NN];
__device__ float g_nd[NN];
__device__ int   g_row_ptr[NN + 1];
__device__ int   g_cursor[NN];
__device__ int   g_csr_src[EE];
__device__ int   g_bsum[128];
__device__ int   g_boff[128];
__device__ float g_bn_sum[LL][DD];
__device__ float g_bn_sq[LL][DD];
__device__ float g_pool_sum[GG * DD];
__device__ float g_pool_cnt[GG];

// ---------------- init ----------
__global__ void k_init() {
    int i = blockIdx.x * blockDim.x + threadIdx.x;
    int stride = gridDim.x * blockDim.x;
    for (int j = i; j < NN; j += stride) { g_out_deg[j] = 0; g_in_deg[j] = 0; }
    for (int j = i; j < LL * DD; j += stride) {
        ((float*)g_bn_sum)[j] = 0.f;
        ((float*)g_bn_sq)[j] = 0.f;
    }
    for (int j = i; j < GG * DD; j += stride) g_pool_sum[j] = 0.f;
    for (int j = i; j < GG; j += stride) g_pool_cnt[j] = 0.f;
}

// ---------------- degree counting ----------
__global__ void k_degree(const int* __restrict__ src, const int* __restrict__ dst) {
    int i = blockIdx.x * blockDim.x + threadIdx.x;
    if (i < EE) {
        atomicAdd(&g_out_deg[src[i]], 1);
        atomicAdd(&g_in_deg[dst[i]], 1);
    }
}

// ---------------- 3-phase scan of in-degree -> row_ptr ----------
__global__ __launch_bounds__(1024) void k_scan1() {
    __shared__ int wsum[32];
    int tid = threadIdx.x, lane = tid & 31, wid = tid >> 5;
    int i = blockIdx.x * 1024 + tid;
    int v = (i < NN) ? g_in_deg[i] : 0;
    int incl = v;
#pragma unroll
    for (int off = 1; off < 32; off <<= 1) {
        int t = __shfl_up_sync(0xffffffffu, incl, off);
        if (lane >= off) incl += t;
    }
    if (lane == 31) wsum[wid] = incl;
    __syncthreads();
    if (wid == 0) {
        int s = wsum[lane];
#pragma unroll
        for (int off = 1; off < 32; off <<= 1) {
            int t = __shfl_up_sync(0xffffffffu, s, off);
            if (lane >= off) s += t;
        }
        wsum[lane] = s;
    }
    __syncthreads();
    int excl = (wid ? wsum[wid - 1] : 0) + incl - v;
    if (i < NN) g_row_ptr[i] = excl;          // block-local exclusive
    if (tid == 0) g_bsum[blockIdx.x] = wsum[31];
}

__global__ void k_scan2() {
    __shared__ int s[128];
    int t = threadIdx.x;
    int v = (t < NB) ? g_bsum[t] : 0;
    s[t] = v;
    __syncthreads();
    // Hillis-Steele inclusive scan over 128
    for (int off = 1; off < 128; off <<= 1) {
        int a = (t >= off) ? s[t - off] : 0;
        __syncthreads();
        s[t] += a;
        __syncthreads();
    }
    g_boff[t] = s[t] - v;                      // exclusive
    if (t == NB - 1) g_row_ptr[NN] = s[t];
}

// phase 3 fused with norms + (ns,x) packing
__global__ __launch_bounds__(1024) void k_scan3(const int* __restrict__ x) {
    int i = blockIdx.x * 1024 + threadIdx.x;
    if (i < NN) {
        int rp = g_row_ptr[i] + g_boff[blockIdx.x];
        g_row_ptr[i] = rp;
        g_cursor[i] = rp;
        float ns = rsqrtf((float)max(g_out_deg[i], 1));
        g_ns[i] = ns;
        g_nd[i] = rsqrtf((float)max(g_in_deg[i], 1));
        g_xns[i] = make_float2(ns, __int_as_float(x[i]));
    }
}

// ---------------- CSR fill ----------
__global__ void k_fill(const int* __restrict__ src, const int* __restrict__ dst) {
    int i = blockIdx.x * blockDim.x + threadIdx.x;
    if (i < EE) {
        int d = dst[i];
        int p = atomicAdd(&g_cursor[d], 1);
        g_csr_src[p] = src[i];
    }
}

// ---------------- EW0 = embed @ W0  (28 x 128) ----------
__global__ void k_ew0(const float* __restrict__ embed, const float* __restrict__ W0) {
    int a = blockIdx.x;
    int f = threadIdx.x;
    float acc = 0.f;
#pragma unroll 8
    for (int k = 0; k < DD; k++)
        acc = fmaf(embed[a * DD + k], W0[k * DD + f], acc);
    g_ew0[a * DD + f] = acc;
}

// ---------------- layer-0 fused lookup-aggregate ----------
__global__ void k_agg0(const float* __restrict__ bs,
                       const float* __restrict__ snorm_n) {
    __shared__ float s_ew[AA * DD];
    __shared__ float s_sum[8][DD];
    __shared__ float s_sq[8][DD];
    int tid = threadIdx.x;
    int w = tid >> 5;
    int lane = tid & 31;
    int node = blockIdx.x * 8 + w;

    for (int i = tid; i < AA * DD; i += 256) s_ew[i] = g_ew0[i];
    __syncthreads();

    float4 r = {0.f, 0.f, 0.f, 0.f};
    if (node < NN) {
        float4 acc = {0.f, 0.f, 0.f, 0.f};
        int start = g_row_ptr[node];
        int end = g_row_ptr[node + 1];
        for (int base = start; base < end; base += 32) {
            int e = base + lane;
            float2 xn = {0.f, 0.f};
            if (e < end) xn = g_xns[g_csr_src[e]];
            int cnt = min(32, end - base);
            for (int j = 0; j < cnt; j++) {
                float nj = __shfl_sync(0xffffffffu, xn.x, j);
                int xj = __shfl_sync(0xffffffffu, __float_as_int(xn.y), j);
                float4 v = *(const float4*)&s_ew[xj * DD + lane * 4];
                acc.x = fmaf(v.x, nj, acc.x);
                acc.y = fmaf(v.y, nj, acc.y);
                acc.z = fmaf(v.z, nj, acc.z);
                acc.w = fmaf(v.w, nj, acc.w);
            }
        }
        float ndv = g_nd[node];
        float sn = snorm_n[node];
        float4 b = *(const float4*)&bs[lane * 4];
        r.x = fmaf(acc.x, ndv, b.x) * sn;
        r.y = fmaf(acc.y, ndv, b.y) * sn;
        r.z = fmaf(acc.z, ndv, b.z) * sn;
        r.w = fmaf(acc.w, ndv, b.w) * sn;
        *(float4*)&g_bufA[node * DD + lane * 4] = r;
    }
    int f0 = lane * 4;
    s_sum[w][f0] = r.x; s_sum[w][f0 + 1] = r.y; s_sum[w][f0 + 2] = r.z; s_sum[w][f0 + 3] = r.w;
    s_sq[w][f0] = r.x * r.x; s_sq[w][f0 + 1] = r.y * r.y;
    s_sq[w][f0 + 2] = r.z * r.z; s_sq[w][f0 + 3] = r.w * r.w;
    __syncthreads();
    if (tid < DD) {
        float s = 0.f, q = 0.f;
#pragma unroll
        for (int ww = 0; ww < 8; ww++) { s += s_sum[ww][tid]; q += s_sq[ww][tid]; }
        atomicAdd(&g_bn_sum[0][tid], s);
        atomicAdd(&g_bn_sq[0][tid], q);
    }
}

// ---------------- 3xBF16 tensor-core GEMM (layers 1..7) --------------------
__device__ __forceinline__ void mma_bf16(float* c, uint32_t a0, uint32_t a1,
                                         uint32_t a2, uint32_t a3,
                                         uint32_t b0, uint32_t b1) {
    asm volatile(
        "mma.sync.aligned.m16n8k16.row.col.f32.bf16.bf16.f32 "
        "{%0,%1,%2,%3}, {%4,%5,%6,%7}, {%8,%9}, {%0,%1,%2,%3};\n"
        : "+f"(c[0]), "+f"(c[1]), "+f"(c[2]), "+f"(c[3])
        : "r"(a0), "r"(a1), "r"(a2), "r"(a3), "r"(b0), "r"(b1));
}

__device__ __forceinline__ uint32_t pack_bf16(float x, float y) {
    uint32_t r;
    asm("cvt.rn.bf16x2.f32 %0, %1, %2;" : "=r"(r) : "f"(y), "f"(x));
    return r;
}

__device__ __forceinline__ void split2(float x, float y, uint32_t& hi, uint32_t& lo) {
    hi = pack_bf16(x, y);
    float hx = __uint_as_float(hi << 16);
    float hy = __uint_as_float(hi & 0xffff0000u);
    lo = pack_bf16(x - hx, y - hy);
}

#define PSTR 18

__global__ __launch_bounds__(256) void k_gemm(const float* __restrict__ W,
                                              const float* __restrict__ gammas,
                                              const float* __restrict__ betas,
                                              int layer) {
    __shared__ uint32_t As_hi[128 * PSTR];
    __shared__ uint32_t As_lo[128 * PSTR];
    __shared__ uint32_t Wt_hi[128 * PSTR];
    __shared__ uint32_t Wt_lo[128 * PSTR];
    __shared__ float s_scale[DD];
    __shared__ float s_shift[DD];

    int tid = threadIdx.x;
    int wid = tid >> 5;
    int lane = tid & 31;
    int g = lane >> 2;
    int tig = lane & 3;
    int row0 = blockIdx.x * 128;
    int wrow = wid * 16;

    // BN scale/shift for (layer-1)
    if (tid < DD) {
        float mean = g_bn_sum[layer - 1][tid] * (1.f / NN);
        float var = g_bn_sq[layer - 1][tid] * (1.f / NN) - mean * mean;
        float rstd = rsqrtf(var + EPSF);
        float sc = rstd * gammas[(layer - 1) * DD + tid];
        s_scale[tid] = sc;
        s_shift[tid] = betas[(layer - 1) * DD + tid] - mean * sc;
    }
    __syncthreads();

    float c[16][4];
#pragma unroll
    for (int i = 0; i < 16; i++)
#pragma unroll
        for (int j = 0; j < 4; j++) c[i][j] = 0.f;

    for (int k0 = 0; k0 < DD; k0 += 32) {
        for (int idx = tid; idx < 128 * 8; idx += 256) {
            int r = idx >> 3;
            int k4 = (idx & 7) * 4;
            int row = row0 + r;
            float4 v = {0.f, 0.f, 0.f, 0.f};
            if (row < NN) {
                v = *(const float4*)&g_bufA[row * DD + k0 + k4];
                v.x = tanhf(fmaf(v.x, s_scale[k0 + k4 + 0], s_shift[k0 + k4 + 0]));
                v.y = tanhf(fmaf(v.y, s_scale[k0 + k4 + 1], s_shift[k0 + k4 + 1]));
                v.z = tanhf(fmaf(v.z, s_scale[k0 + k4 + 2], s_shift[k0 + k4 + 2]));
                v.w = tanhf(fmaf(v.w, s_scale[k0 + k4 + 3], s_shift[k0 + k4 + 3]));
            }
            uint32_t h01, l01, h23, l23;
            split2(v.x, v.y, h01, l01);
            split2(v.z, v.w, h23, l23);
            int p = r * PSTR + (k4 >> 1);
            As_hi[p] = h01; As_hi[p + 1] = h23;
            As_lo[p] = l01; As_lo[p + 1] = l23;
        }
        for (int idx = tid; idx < 16 * DD; idx += 256) {
            int n = idx & 127;
            int kp = idx >> 7;
            float w0 = W[(k0 + 2 * kp) * DD + n];
            float w1 = W[(k0 + 2 * kp + 1) * DD + n];
            uint32_t h, l;
            split2(w0, w1, h, l);
            Wt_hi[n * PSTR + kp] = h;
            Wt_lo[n * PSTR + kp] = l;
        }
        __syncthreads();
#pragma unroll
        for (int ks = 0; ks < 2; ks++) {
            int kb = ks * 8;
            int ra = (wrow + g) * PSTR + kb + tig;
            int rb = (wrow + g + 8) * PSTR + kb + tig;
            uint32_t ah0 = As_hi[ra],     ah1 = As_hi[rb];
            uint32_t ah2 = As_hi[ra + 4], ah3 = As_hi[rb + 4];
            uint32_t al0 = As_lo[ra],     al1 = As_lo[rb];
            uint32_t al2 = As_lo[ra + 4], al3 = As_lo[rb + 4];
#pragma unroll
            for (int nt = 0; nt < 16; nt++) {
                int wb = (nt * 8 + g) * PSTR + kb + tig;
                uint32_t bh0 = Wt_hi[wb], bh1 = Wt_hi[wb + 4];
                uint32_t bl0 = Wt_lo[wb], bl1 = Wt_lo[wb + 4];
                mma_bf16(c[nt], al0, al1, al2, al3, bh0, bh1);
                mma_bf16(c[nt], ah0, ah1, ah2, ah3, bl0, bl1);
                mma_bf16(c[nt], ah0, ah1, ah2, ah3, bh0, bh1);
            }
        }
        __syncthreads();
    }
    int rA = row0 + wrow + g;
    int rB = rA + 8;
    float nsA = (rA < NN) ? g_ns[rA] : 0.f;
    float nsB = (rB < NN) ? g_ns[rB] : 0.f;
#pragma unroll
    for (int nt = 0; nt < 16; nt++) {
        int col = nt * 8 + tig * 2;
        if (rA < NN) {
            float2 o = {c[nt][0] * nsA, c[nt][1] * nsA};
            *(float2*)&g_bufB[rA * DD + col] = o;
        }
        if (rB < NN) {
            float2 o = {c[nt][2] * nsB, c[nt][3] * nsB};
            *(float2*)&g_bufB[rB * DD + col] = o;
        }
    }
}

// ---------------- aggregate + fused BN stats (layers 1..7) ------------------
__global__ void k_agg(const float* __restrict__ bs,
                      const float* __restrict__ snorm_n,
                      int layer) {
    __shared__ float s_sum[8][DD];
    __shared__ float s_sq[8][DD];
    int w = threadIdx.x >> 5;
    int lane = threadIdx.x & 31;
    int node = blockIdx.x * 8 + w;

    float4 r = {0.f, 0.f, 0.f, 0.f};
    if (node < NN) {
        float4 acc = {0.f, 0.f, 0.f, 0.f};
        int start = g_row_ptr[node];
        int end = g_row_ptr[node + 1];
        for (int base = start; base < end; base += 32) {
            int e = base + lane;
            int s = (e < end) ? g_csr_src[e] : 0;
            int cnt = min(32, end - base);
            int j = 0;
            for (; j + 8 <= cnt; j += 8) {
                int s0 = __shfl_sync(0xffffffffu, s, j);
                int s1 = __shfl_sync(0xffffffffu, s, j + 1);
                int s2 = __shfl_sync(0xffffffffu, s, j + 2);
                int s3 = __shfl_sync(0xffffffffu, s, j + 3);
                int s4 = __shfl_sync(0xffffffffu, s, j + 4);
                int s5 = __shfl_sync(0xffffffffu, s, j + 5);
                int s6 = __shfl_sync(0xffffffffu, s, j + 6);
                int s7 = __shfl_sync(0xffffffffu, s, j + 7);
                float4 v0 = *(const float4*)&g_bufB[s0 * DD + lane * 4];
                float4 v1 = *(const float4*)&g_bufB[s1 * DD + lane * 4];
                float4 v2 = *(const float4*)&g_bufB[s2 * DD + lane * 4];
                float4 v3 = *(const float4*)&g_bufB[s3 * DD + lane * 4];
                float4 v4 = *(const float4*)&g_bufB[s4 * DD + lane * 4];
                float4 v5 = *(const float4*)&g_bufB[s5 * DD + lane * 4];
                float4 v6 = *(const float4*)&g_bufB[s6 * DD + lane * 4];
                float4 v7 = *(const float4*)&g_bufB[s7 * DD + lane * 4];
                acc.x += ((v0.x + v1.x) + (v2.x + v3.x)) + ((v4.x + v5.x) + (v6.x + v7.x));
                acc.y += ((v0.y + v1.y) + (v2.y + v3.y)) + ((v4.y + v5.y) + (v6.y + v7.y));
                acc.z += ((v0.z + v1.z) + (v2.z + v3.z)) + ((v4.z + v5.z) + (v6.z + v7.z));
                acc.w += ((v0.w + v1.w) + (v2.w + v3.w)) + ((v4.w + v5.w) + (v6.w + v7.w));
            }
            for (; j < cnt; j++) {
                int sj = __shfl_sync(0xffffffffu, s, j);
                float4 v = *(const float4*)&g_bufB[sj * DD + lane * 4];
                acc.x += v.x; acc.y += v.y; acc.z += v.z; acc.w += v.w;
            }
        }
        float ndv = g_nd[node];
        float sn = snorm_n[node];
        float4 b = *(const float4*)&bs[layer * DD + lane * 4];
        r.x = fmaf(acc.x, ndv, b.x) * sn;
        r.y = fmaf(acc.y, ndv, b.y) * sn;
        r.z = fmaf(acc.z, ndv, b.z) * sn;
        r.w = fmaf(acc.w, ndv, b.w) * sn;
        *(float4*)&g_bufA[node * DD + lane * 4] = r;
    }
    int f0 = lane * 4;
    s_sum[w][f0] = r.x; s_sum[w][f0 + 1] = r.y; s_sum[w][f0 + 2] = r.z; s_sum[w][f0 + 3] = r.w;
    s_sq[w][f0] = r.x * r.x; s_sq[w][f0 + 1] = r.y * r.y;
    s_sq[w][f0 + 2] = r.z * r.z; s_sq[w][f0 + 3] = r.w * r.w;
    __syncthreads();
    if (threadIdx.x < DD) {
        int f = threadIdx.x;
        float s = 0.f, q = 0.f;
#pragma unroll
        for (int ww = 0; ww < 8; ww++) { s += s_sum[ww][f]; q += s_sq[ww][f]; }
        atomicAdd(&g_bn_sum[layer][f], s);
        atomicAdd(&g_bn_sq[layer][f], q);
    }
}

// ---------------- graph mean pooling (graph_ids sorted); BN folded in ------
__global__ void k_pool(const int* __restrict__ gid,
                       const float* __restrict__ gammas,
                       const float* __restrict__ betas) {
    int f = threadIdx.x;
    int base = blockIdx.x * 32;
    float mean = g_bn_sum[LL - 1][f] * (1.f / NN);
    float var = g_bn_sq[LL - 1][f] * (1.f / NN) - mean * mean;
    float rstd = rsqrtf(var + EPSF);
    float sc = rstd * gammas[(LL - 1) * DD + f];
    float sh = betas[(LL - 1) * DD + f] - mean * sc;

    float acc = 0.f;
    int cur = gid[base];
    for (int i = 0; i < 32; i++) {
        int node = base + i;
        if (node >= NN) break;
        int g = gid[node];
        if (g != cur) {
            atomicAdd(&g_pool_sum[cur * DD + f], acc);
            acc = 0.f;
            cur = g;
        }
        float v = g_bufA[node * DD + f];
        acc += tanhf(fmaf(v, sc, sh));
    }
    atomicAdd(&g_pool_sum[cur * DD + f], acc);
    if (f == 0) {
        float c = 0.f;
        int cur2 = gid[base];
        for (int i = 0; i < 32; i++) {
            int node = base + i;
            if (node >= NN) break;
            int g = gid[node];
            if (g != cur2) {
                atomicAdd(&g_pool_cnt[cur2], c);
                c = 0.f;
                cur2 = g;
            }
            c += 1.f;
        }
        atomicAdd(&g_pool_cnt[cur2], c);
    }
}

// ---------------- readout MLP ----------
__global__ void k_mlp(const float* __restrict__ r1w, const float* __restrict__ r1b,
                      const float* __restrict__ r2w, const float* __restrict__ r2b,
                      float* __restrict__ out) {
    __shared__ float hg[DD];
    __shared__ float z[64];
    int g = blockIdx.x;
    int t = threadIdx.x;
    float cnt = fmaxf(g_pool_cnt[g], 1.f);
    for (int f = t; f < DD; f += 64)
        hg[f] = fmaxf(g_pool_sum[g * DD + f] / cnt, 0.f);
    __syncthreads();
    float d = r1b[t];
#pragma unroll 8
    for (int f = 0; f < DD; f++) d = fmaf(hg[f], r1w[t * DD + f], d);
    z[t] = fmaxf(d, 0.f);
    __syncthreads();
    if (t == 0) {
        float o = r2b[0];
#pragma unroll 8
        for (int i = 0; i < 64; i++) o = fmaf(z[i], r2w[i], o);
        out[g] = o;
    }
}

// ---------------- host ----------
extern "C" void kernel_launch(void* const* d_in, const int* in_sizes, int n_in,
                              void* d_out, int out_size) {
    const int* x = (const int*)d_in[0];
    const int* src = (const int*)d_in[2];
    const int* dst = (const int*)d_in[3];
    const int* gid = (const int*)d_in[4];
    const float* snorm_n = (const float*)d_in[5];
    const float* embed = (const float*)d_in[7];
    const float* Ws = (const float*)d_in[8];
    const float* bs = (const float*)d_in[9];
    const float* gammas = (const float*)d_in[10];
    const float* betas = (const float*)d_in[11];
    const float* r1w = (const float*)d_in[12];
    const float* r1b = (const float*)d_in[13];
    const float* r2w = (const float*)d_in[14];
    const float* r2b = (const float*)d_in[15];
    float* out = (float*)d_out;

    k_init<<<256, 256>>>();
    k_ew0<<<AA, DD>>>(embed, Ws);
    k_degree<<<(EE + 255) / 256, 256>>>(src, dst);
    k_scan1<<<NB, 1024>>>();
    k_scan2<<<1, 128>>>();
    k_scan3<<<NB, 1024>>>(x);
    k_fill<<<(EE + 255) / 256, 256>>>(src, dst);

    // layer 0: exact fused lookup-aggregate
    k_agg0<<<(NN + 7) / 8, 256>>>(bs, snorm_n);

    for (int l = 1; l < LL; l++) {
        k_gemm<<<(NN + 127) / 128, 256>>>(Ws + l * DD * DD, gammas, betas, l);
        k_agg<<<(NN + 7) / 8, 256>>>(bs, snorm_n, l);
    }
    k_pool<<<(NN + 31) / 32, DD>>>(gid, gammas, betas);
    k_mlp<<<GG, 64>>>(r1w, r1b, r2w, r2b, out);
}